// round 13
// baseline (speedup 1.0000x reference)
#include <cuda_runtime.h>
#include <cuda_fp16.h>
#include <cstdint>
#include <cfloat>

// ---------------- problem constants ----------------
#define SPATIAL   4096
#define DIM       64
#define NCODES    1024
#define Q_ELEMS   4194304
#define OUT_LOSS_OFF 0
#define OUT_Q_OFF    1
#define OUT_IDX_OFF  (1 + Q_ELEMS)

#define TILE_M    128           // positions per CTA (1 m16 slab per warp)
#define CHUNK     128           // codes per smem chunk
#define NCHUNKS   (NCODES / CHUNK)
#define ESTRIDE   72            // halves per row (144B): conflict-free LDS/LDSM
#define CAP       16            // candidate list capacity per position

// smem layout (byte offsets)
#define BUF0_OFF   0u           // E-hi chunk buf0 (18432)
#define BUF1_OFF   18432u       // E-hi chunk buf1; also A-hi staging (128x72 half)
#define SM_NEB     36864u       // 1024 floats
#define SM_EPS     40960u       // 128 floats
#define SM_SNORM   41472u       // 128 floats
#define SM_LIST    41984u       // 128 x 16 u16 = 4096
#define SM_CNT     46080u       // 128 u32
#define SM_SBK     46592u       // 128 ints
#define SM_RED     47104u       // 8 floats
#define SMEM_BYTES 47168

// ---------------- device scratch ----------------
__device__ __align__(16) __half g_ehi[NCODES * ESTRIDE];  // fl16(e), padded rows
__device__ float g_neb[NCODES];     // -0.5 * ||e_k||^2 (fp32)
__device__ int   g_emaxbits;        // max ||e_k|| as float bits

// ---------------- PTX helpers ----------------
__device__ __forceinline__ uint32_t smem_u32(const void* p) {
    uint32_t a;
    asm("{ .reg .u64 t; cvta.to.shared.u64 t, %1; cvt.u32.u64 %0, t; }" : "=r"(a) : "l"(p));
    return a;
}
#define CP16(dst, src)  asm volatile("cp.async.cg.shared.global [%0], [%1], 16;" :: "r"(dst), "l"(src))
#define CP_COMMIT()     asm volatile("cp.async.commit_group;" ::: "memory")
#define CP_WAIT0()      asm volatile("cp.async.wait_group 0;" ::: "memory")

__device__ __forceinline__ void ldsm_x4(uint32_t& r0, uint32_t& r1, uint32_t& r2,
                                        uint32_t& r3, uint32_t addr) {
    asm volatile("ldmatrix.sync.aligned.m8n8.x4.shared.b16 {%0,%1,%2,%3}, [%4];"
                 : "=r"(r0), "=r"(r1), "=r"(r2), "=r"(r3) : "r"(addr));
}
__device__ __forceinline__ void mma_init(float& d0, float& d1, float& d2, float& d3,
                                         const uint32_t* a, uint32_t b0, uint32_t b1,
                                         float cx, float cy) {
    asm volatile("mma.sync.aligned.m16n8k16.row.col.f32.f16.f16.f32 "
                 "{%0,%1,%2,%3}, {%4,%5,%6,%7}, {%8,%9}, {%10,%11,%10,%11};"
                 : "=f"(d0), "=f"(d1), "=f"(d2), "=f"(d3)
                 : "r"(a[0]), "r"(a[1]), "r"(a[2]), "r"(a[3]), "r"(b0), "r"(b1),
                   "f"(cx), "f"(cy));
}
__device__ __forceinline__ void mma_acc(float& d0, float& d1, float& d2, float& d3,
                                        const uint32_t* a, uint32_t b0, uint32_t b1) {
    asm volatile("mma.sync.aligned.m16n8k16.row.col.f32.f16.f16.f32 "
                 "{%0,%1,%2,%3}, {%4,%5,%6,%7}, {%8,%9}, {%0,%1,%2,%3};"
                 : "+f"(d0), "+f"(d1), "+f"(d2), "+f"(d3)
                 : "r"(a[0]), "r"(a[1]), "r"(a[2]), "r"(a[3]), "r"(b0), "r"(b1));
}

// ---------------------------------------------------------------------------
// Kernel 1: E -> f16 hi (padded rows); neb; Emax; zero loss slot.
// ---------------------------------------------------------------------------
__global__ void vq_prep_kernel(const float* __restrict__ emb, float* __restrict__ out) {
    int r = blockIdx.x * blockDim.x + threadIdx.x;
    if (r == 0) out[OUT_LOSS_OFF] = 0.0f;
    if (r >= NCODES) return;
    const float* e = emb + (size_t)r * DIM;
    float s = 0.0f;
#pragma unroll
    for (int c = 0; c < DIM; c++) {
        float v = e[c];
        s += v * v;
        g_ehi[r * ESTRIDE + c] = __float2half_rn(v);
    }
    g_neb[r] = -0.5f * s;
    atomicMax(&g_emaxbits, __float_as_int(sqrtf(s)));
}

__device__ __forceinline__ void copy_chunk(uint32_t smb, int chunkid, int buf, int t) {
    const uint32_t dst = smb + (buf ? BUF1_OFF : BUF0_OFF);
    const char* src = (const char*)(g_ehi + (size_t)chunkid * CHUNK * ESTRIDE);
#pragma unroll
    for (int i = t; i < 1152; i += 256) CP16(dst + 16u * i, src + (size_t)i * 16);
}

// ---------------------------------------------------------------------------
// Kernel 2: two-pass hi-only HMMA screen (short chains, high occ) + rescore.
// ---------------------------------------------------------------------------
__global__ void __launch_bounds__(256, 3) vq_main_kernel(
    const float* __restrict__ x_in,   // [16,64,64,64] NCHW
    const float* __restrict__ emb,    // [1024,64] f32
    float* __restrict__ out)
{
    extern __shared__ char sm[];
    const uint32_t smb = smem_u32(sm);
    __half* aHi = (__half*)(sm + BUF1_OFF);             // A staging == buf1
    float*  sneb  = (float*)(sm + SM_NEB);
    float*  seps  = (float*)(sm + SM_EPS);
    float*  snorm = (float*)(sm + SM_SNORM);
    unsigned short* slist = (unsigned short*)(sm + SM_LIST);
    unsigned int*   scnt  = (unsigned int*)(sm + SM_CNT);
    int*    sbk   = (int*)(sm + SM_SBK);
    float*  sred  = (float*)(sm + SM_RED);

    const int t    = threadIdx.x;
    const int lane = t & 31;
    const int w    = t >> 5;
    const int g    = lane >> 2;
    const int q    = lane & 3;
    const int tile = blockIdx.x;
    const int b_idx = tile >> 5;               // 32 tiles per image
    const int s0    = (tile & 31) * TILE_M;
    const float* xbase = x_in + (size_t)b_idx * (DIM * SPATIAL) + s0;

    copy_chunk(smb, 0, 0, t);
    CP_COMMIT();

    // --- stage X (128 pos) as f16-hi; ||x||^2 ---
    {
        const int p = t & 127, ch = t >> 7;
        const float* xp = xbase + p;
        float n2 = 0.0f;
#pragma unroll
        for (int i = 0; i < 32; i++) {
            int c = ch * 32 + i;
            float v = xp[c * SPATIAL];
            n2 += v * v;
            aHi[p * ESTRIDE + c] = __float2half_rn(v);
        }
        if (ch == 0) snorm[p] = n2;
        __syncthreads();
        if (ch == 1) snorm[p] += n2;
    }
    // --- extract A-hi fragments (one slab: rows w*16..w*16+15) ---
    const int m0 = w * 16;
    uint32_t AH[4][4];
    {
        const uint32_t r0 = (uint32_t)(m0 + g) * ESTRIDE;
        const uint32_t r8 = r0 + 8 * ESTRIDE;
#pragma unroll
        for (int ks = 0; ks < 4; ks++) {
            int c0 = 16 * ks + 2 * q;
            AH[ks][0] = *(const uint32_t*)&aHi[r0 + c0];
            AH[ks][1] = *(const uint32_t*)&aHi[r8 + c0];
            AH[ks][2] = *(const uint32_t*)&aHi[r0 + c0 + 8];
            AH[ks][3] = *(const uint32_t*)&aHi[r8 + c0 + 8];
        }
    }
    __syncthreads();   // frags + snorm done; buf1 free
    {
        const float Emax = __int_as_float(g_emaxbits);
        if (t < 128) seps[t] = 1.954e-3f * sqrtf(snorm[t]) * Emax + 4e-3f;
        for (int i = t; i < NCODES; i += 256) sneb[i] = g_neb[i];
    }

    const uint32_t lmoff = (uint32_t)(((lane & 7) * ESTRIDE + (lane >> 3) * 8) * 2);
    const int r0i = m0 + g, r1i = m0 + g + 8;

    float bv0 = -FLT_MAX, bv1 = -FLT_MAX;
    float thr0 = 0.0f, thr1 = 0.0f;

    for (int c = 0; c < 2 * NCHUNKS; c++) {
        const int chunkid = c & 7, buf = c & 1, pass2 = c >> 3;
        CP_WAIT0();
        if (c == 8) {
            if (t < 128) scnt[t] = 0u;
#pragma unroll
            for (int m = 1; m < 4; m <<= 1) {
                bv0 = fmaxf(bv0, __shfl_xor_sync(0xffffffffu, bv0, m));
                bv1 = fmaxf(bv1, __shfl_xor_sync(0xffffffffu, bv1, m));
            }
            thr0 = bv0 - seps[r0i];
            thr1 = bv1 - seps[r1i];
        }
        __syncthreads();
        if (c + 1 < 2 * NCHUNKS) { copy_chunk(smb, (c + 1) & 7, (c + 1) & 1, t); CP_COMMIT(); }

        const uint32_t bhi = smb + (buf ? BUF1_OFF : BUF0_OFF) + lmoff;
        const float* nebc = sneb + chunkid * CHUNK + 2 * q;
        const int kbase = chunkid * CHUNK;

        for (int n16 = 0; n16 < 8; n16++) {        // 2 n8-groups per iter
            const uint32_t adv = (uint32_t)n16 * 2304u;
            uint32_t ha0, ha1, ha2, ha3, ha4, ha5, ha6, ha7;
            uint32_t hb0, hb1, hb2, hb3, hb4, hb5, hb6, hb7;
            ldsm_x4(ha0, ha1, ha2, ha3, bhi + adv);
            ldsm_x4(ha4, ha5, ha6, ha7, bhi + adv + 64u);
            ldsm_x4(hb0, hb1, hb2, hb3, bhi + adv + 1152u);
            ldsm_x4(hb4, hb5, hb6, hb7, bhi + adv + 1152u + 64u);
            float2 nbA = *(const float2*)(nebc + n16 * 16);
            float2 nbB = *(const float2*)(nebc + n16 * 16 + 8);

            // 4 independent 4-deep chains (2 per n8-group)
            float p0, p1, p2, p3, u0, u1, u2, u3;     // group A
            float s0v, s1v, s2v, s3v, v0, v1, v2, v3; // group B
            mma_init(p0, p1, p2, p3, AH[0], ha0, ha1, nbA.x, nbA.y);
            mma_init(s0v, s1v, s2v, s3v, AH[0], hb0, hb1, nbB.x, nbB.y);
            mma_init(u0, u1, u2, u3, AH[2], ha4, ha5, 0.0f, 0.0f);
            mma_init(v0, v1, v2, v3, AH[2], hb4, hb5, 0.0f, 0.0f);
            mma_acc (p0, p1, p2, p3, AH[1], ha2, ha3);
            mma_acc (s0v, s1v, s2v, s3v, AH[1], hb2, hb3);
            mma_acc (u0, u1, u2, u3, AH[3], ha6, ha7);
            mma_acc (v0, v1, v2, v3, AH[3], hb6, hb7);
            const float a0 = p0 + u0, a1 = p1 + u1, a2 = p2 + u2, a3 = p3 + u3;
            const float b0 = s0v + v0, b1 = s1v + v1, b2 = s2v + v2, b3 = s3v + v3;

            if (!pass2) {
                bv0 = fmaxf(bv0, fmaxf(fmaxf(a0, a1), fmaxf(b0, b1)));
                bv1 = fmaxf(bv1, fmaxf(fmaxf(a2, a3), fmaxf(b2, b3)));
            } else {
                const int kA = kbase + n16 * 16 + 2 * q;
                const int kB = kA + 8;
                if (a0 >= thr0) { unsigned i = atomicAdd(&scnt[r0i], 1u); if (i < CAP) slist[r0i * CAP + i] = (unsigned short)kA; }
                if (a1 >= thr0) { unsigned i = atomicAdd(&scnt[r0i], 1u); if (i < CAP) slist[r0i * CAP + i] = (unsigned short)(kA + 1); }
                if (b0 >= thr0) { unsigned i = atomicAdd(&scnt[r0i], 1u); if (i < CAP) slist[r0i * CAP + i] = (unsigned short)kB; }
                if (b1 >= thr0) { unsigned i = atomicAdd(&scnt[r0i], 1u); if (i < CAP) slist[r0i * CAP + i] = (unsigned short)(kB + 1); }
                if (a2 >= thr1) { unsigned i = atomicAdd(&scnt[r1i], 1u); if (i < CAP) slist[r1i * CAP + i] = (unsigned short)kA; }
                if (a3 >= thr1) { unsigned i = atomicAdd(&scnt[r1i], 1u); if (i < CAP) slist[r1i * CAP + i] = (unsigned short)(kA + 1); }
                if (b2 >= thr1) { unsigned i = atomicAdd(&scnt[r1i], 1u); if (i < CAP) slist[r1i * CAP + i] = (unsigned short)kB; }
                if (b3 >= thr1) { unsigned i = atomicAdd(&scnt[r1i], 1u); if (i < CAP) slist[r1i * CAP + i] = (unsigned short)(kB + 1); }
            }
        }
    }
    __syncthreads();   // all appends visible

    // --- exact fp32 rescore (threads 0..127, one per position) ---
    if (t < 128) {
        const int p = t;
        const float* xp = xbase + p;
        const unsigned cnt = scnt[p];
        float bestv = -FLT_MAX;
        int bestk = 0;
        if (cnt <= CAP) {
            for (unsigned i = 0; i < cnt; i++) {
                const int k = slist[p * CAP + i];
                const float4* er = (const float4*)(emb + (size_t)k * DIM);
                float v = sneb[k];
#pragma unroll
                for (int j = 0; j < 16; j++) {
                    float4 e4 = er[j];
                    int cc = 4 * j;
                    v += xp[(cc + 0) * SPATIAL] * e4.x + xp[(cc + 1) * SPATIAL] * e4.y
                       + xp[(cc + 2) * SPATIAL] * e4.z + xp[(cc + 3) * SPATIAL] * e4.w;
                }
                if (v > bestv || (v == bestv && k < bestk)) { bestv = v; bestk = k; }
            }
        } else {
            for (int k = 0; k < NCODES; k++) {     // overflow fallback (exact)
                const float4* er = (const float4*)(emb + (size_t)k * DIM);
                float v = sneb[k];
#pragma unroll
                for (int j = 0; j < 16; j++) {
                    float4 e4 = er[j];
                    int cc = 4 * j;
                    v += xp[(cc + 0) * SPATIAL] * e4.x + xp[(cc + 1) * SPATIAL] * e4.y
                       + xp[(cc + 2) * SPATIAL] * e4.z + xp[(cc + 3) * SPATIAL] * e4.w;
                }
                if (v > bestv) { bestv = v; bestk = k; }
            }
        }
        sbk[p] = bestk;
        out[OUT_IDX_OFF + (size_t)b_idx * SPATIAL + s0 + p] = (float)bestk;
    }
    __syncthreads();

    // --- gather + exact loss (all 256 threads; p = t&127, ch = t>>7) ---
    {
        const int p = t & 127, ch = t >> 7;
        const float* xp = xbase + p;
        const int bk = sbk[p];
        const float4* er = (const float4*)(emb + (size_t)bk * DIM) + ch * 8;
        float* qo = out + OUT_Q_OFF + (size_t)b_idx * (DIM * SPATIAL) + s0 + p;
        float lsum = 0.0f;
#pragma unroll
        for (int j = 0; j < 8; j++) {
            float4 e4 = er[j];
            int cc = ch * 32 + 4 * j;
            float x0 = xp[(cc + 0) * SPATIAL], x1 = xp[(cc + 1) * SPATIAL];
            float x2 = xp[(cc + 2) * SPATIAL], x3 = xp[(cc + 3) * SPATIAL];
            qo[(cc + 0) * SPATIAL] = e4.x;
            qo[(cc + 1) * SPATIAL] = e4.y;
            qo[(cc + 2) * SPATIAL] = e4.z;
            qo[(cc + 3) * SPATIAL] = e4.w;
            float u0 = e4.x - x0, u1 = e4.y - x1, u2 = e4.z - x2, u3 = e4.w - x3;
            lsum += u0 * u0 + u1 * u1 + u2 * u2 + u3 * u3;
        }
        lsum *= 0.25f / (float)Q_ELEMS;
#pragma unroll
        for (int off = 16; off > 0; off >>= 1)
            lsum += __shfl_down_sync(0xffffffffu, lsum, off);
        if (lane == 0) sred[w] = lsum;
    }
    __syncthreads();
    if (t == 0) {
        float s = 0.0f;
#pragma unroll
        for (int i = 0; i < 8; i++) s += sred[i];
        atomicAdd(out + OUT_LOSS_OFF, s);
    }
}

// ---------------------------------------------------------------------------
extern "C" void kernel_launch(void* const* d_in, const int* in_sizes, int n_in,
                              void* d_out, int out_size) {
    const float* x_in = (const float*)d_in[0];
    const float* emb  = (const float*)d_in[1];
    float* out = (float*)d_out;

    cudaFuncSetAttribute(vq_main_kernel,
                         cudaFuncAttributeMaxDynamicSharedMemorySize, SMEM_BYTES);

    vq_prep_kernel<<<NCODES / 256, 256>>>(emb, out);
    vq_main_kernel<<<(16 * SPATIAL) / TILE_M, 256, SMEM_BYTES>>>(x_in, emb, out);
}

// round 14
// speedup vs baseline: 1.1441x; 1.1441x over previous
#include <cuda_runtime.h>
#include <cuda_fp16.h>
#include <cstdint>
#include <cfloat>

// ---------------- problem constants ----------------
#define SPATIAL   4096
#define DIM       64
#define NCODES    1024
#define Q_ELEMS   4194304
#define OUT_LOSS_OFF 0
#define OUT_Q_OFF    1
#define OUT_IDX_OFF  (1 + Q_ELEMS)

#define TILE_M    128           // positions per CTA (1 m16 slab per warp)
#define CHUNK     128           // codes per smem chunk
#define NCHUNKS   (NCODES / CHUNK)
#define ESTRIDE   72            // halves per row (144B): conflict-free LDS/LDSM

// smem layout (byte offsets). Each buf: [hi 18432 | lo 18432] = 36864 B.
// BUF1 doubles as A staging (A-hi at +0, A-lo at +18432), consumed to regs
// before chunk 1 is copied into it.
#define BUF0_OFF   0u
#define BUF1_OFF   36864u
#define HALF_BUF   18432u
#define SM_SBK     73728u       // 128 ints
#define SM_RED     74240u       // 16 floats: [0..7] sum x^2, [8..15] sum v_best
#define SMEM_BYTES 74304        // x3 CTAs = 222.9 KB < 228 KB

// ---------------- device scratch (pre-split, padded E) ----------------
__device__ __align__(16) __half g_ehi[NCODES * ESTRIDE];
__device__ __align__(16) __half g_elo[NCODES * ESTRIDE];
__device__ float g_neb[NCODES];     // -0.5 * ||e_k||^2

// ---------------- PTX helpers ----------------
__device__ __forceinline__ uint32_t smem_u32(const void* p) {
    uint32_t a;
    asm("{ .reg .u64 t; cvta.to.shared.u64 t, %1; cvt.u32.u64 %0, t; }" : "=r"(a) : "l"(p));
    return a;
}
#define CP16(dst, src)  asm volatile("cp.async.cg.shared.global [%0], [%1], 16;" :: "r"(dst), "l"(src))
#define CP_COMMIT()     asm volatile("cp.async.commit_group;" ::: "memory")
#define CP_WAIT0()      asm volatile("cp.async.wait_group 0;" ::: "memory")

__device__ __forceinline__ void ldsm_x4(uint32_t& r0, uint32_t& r1, uint32_t& r2,
                                        uint32_t& r3, uint32_t addr) {
    asm volatile("ldmatrix.sync.aligned.m8n8.x4.shared.b16 {%0,%1,%2,%3}, [%4];"
                 : "=r"(r0), "=r"(r1), "=r"(r2), "=r"(r3) : "r"(addr));
}
__device__ __forceinline__ void mma_init(float& d0, float& d1, float& d2, float& d3,
                                         const uint32_t* a, uint32_t b0, uint32_t b1,
                                         float cx, float cy) {
    asm volatile("mma.sync.aligned.m16n8k16.row.col.f32.f16.f16.f32 "
                 "{%0,%1,%2,%3}, {%4,%5,%6,%7}, {%8,%9}, {%10,%11,%10,%11};"
                 : "=f"(d0), "=f"(d1), "=f"(d2), "=f"(d3)
                 : "r"(a[0]), "r"(a[1]), "r"(a[2]), "r"(a[3]), "r"(b0), "r"(b1),
                   "f"(cx), "f"(cy));
}
__device__ __forceinline__ void mma_acc(float& d0, float& d1, float& d2, float& d3,
                                        const uint32_t* a, uint32_t b0, uint32_t b1) {
    asm volatile("mma.sync.aligned.m16n8k16.row.col.f32.f16.f16.f32 "
                 "{%0,%1,%2,%3}, {%4,%5,%6,%7}, {%8,%9}, {%0,%1,%2,%3};"
                 : "+f"(d0), "+f"(d1), "+f"(d2), "+f"(d3)
                 : "r"(a[0]), "r"(a[1]), "r"(a[2]), "r"(a[3]), "r"(b0), "r"(b1));
}

// ---------------------------------------------------------------------------
// Kernel 1: split E -> (hi, lo) f16, padded rows; neb; zero loss.
// 8192 threads: 8 threads per code row, 16B vector stores.
// ---------------------------------------------------------------------------
__global__ void vq_prep_kernel(const float* __restrict__ emb, float* __restrict__ out) {
    const int tid = blockIdx.x * blockDim.x + threadIdx.x;   // 0..8191
    if (tid == 0) out[OUT_LOSS_OFF] = 0.0f;
    const int r = tid >> 3, j = tid & 7;
    const float* e = emb + (size_t)r * DIM + j * 8;
    __half hi[8], lo[8];
    float s = 0.0f;
#pragma unroll
    for (int i = 0; i < 8; i++) {
        float v = e[i];
        s += v * v;
        hi[i] = __float2half_rn(v);
        lo[i] = __float2half_rn(v - __half2float(hi[i]));
    }
    *(uint4*)&g_ehi[r * ESTRIDE + j * 8] = *(const uint4*)hi;
    *(uint4*)&g_elo[r * ESTRIDE + j * 8] = *(const uint4*)lo;
#pragma unroll
    for (int off = 4; off > 0; off >>= 1)
        s += __shfl_down_sync(0xffffffffu, s, off, 8);
    if (j == 0) g_neb[r] = -0.5f * s;
}

// ---------------------------------------------------------------------------
// Chunk copy: E chunk (hi 18432 + lo 18432 B) via cp.async 16B.
// ---------------------------------------------------------------------------
__device__ __forceinline__ void copy_chunk(uint32_t smb, int chunkid, int buf, int t) {
    const uint32_t dst = smb + (buf ? BUF1_OFF : BUF0_OFF);
    const char* srcH = (const char*)(g_ehi + (size_t)chunkid * CHUNK * ESTRIDE);
    const char* srcL = (const char*)(g_elo + (size_t)chunkid * CHUNK * ESTRIDE);
#pragma unroll
    for (int i = t; i < 1152; i += 256) {
        CP16(dst + 16u * i, srcH + (size_t)i * 16);
        CP16(dst + HALF_BUF + 16u * i, srcL + (size_t)i * 16);
    }
}

// ---------------------------------------------------------------------------
// Kernel 2: exact 3-term HMMA GEMM + argmin + gather + loss.
// 128 positions/CTA, 1 m16 slab per warp, 3 CTAs/SM target.
// ---------------------------------------------------------------------------
__global__ void __launch_bounds__(256, 3) vq_main_kernel(
    const float* __restrict__ x_in,   // [16,64,64,64] NCHW
    const float* __restrict__ emb,    // [1024,64] f32
    float* __restrict__ out)
{
    extern __shared__ char sm[];
    const uint32_t smb = smem_u32(sm);
    __half* aHi = (__half*)(sm + BUF1_OFF);             // A staging == buf1
    __half* aLo = (__half*)(sm + BUF1_OFF + HALF_BUF);
    int*    sbk  = (int*)(sm + SM_SBK);
    float*  sred = (float*)(sm + SM_RED);

    const int t    = threadIdx.x;
    const int lane = t & 31;
    const int w    = t >> 5;
    const int g    = lane >> 2;
    const int q    = lane & 3;
    const int tile = blockIdx.x;
    const int b_idx = tile >> 5;               // 32 tiles per image
    const int s0    = (tile & 31) * TILE_M;
    const float* xbase = x_in + (size_t)b_idx * (DIM * SPATIAL) + s0;

    copy_chunk(smb, 0, 0, t);
    CP_COMMIT();

    // --- stage X (128 pos) as split f16 into BUF1; accumulate sum(x^2) ---
    {
        const int p = t & 127, ch = t >> 7;
        const float* xp = xbase + p;
        float n2 = 0.0f;
#pragma unroll
        for (int i = 0; i < 32; i++) {
            int c = ch * 32 + i;
            float v = xp[c * SPATIAL];
            n2 += v * v;
            __half h = __float2half_rn(v);
            aHi[p * ESTRIDE + c] = h;
            aLo[p * ESTRIDE + c] = __float2half_rn(v - __half2float(h));
        }
#pragma unroll
        for (int off = 16; off > 0; off >>= 1)
            n2 += __shfl_down_sync(0xffffffffu, n2, off);
        if (lane == 0) sred[w] = n2;   // distinct slot per warp
    }
    __syncthreads();

    // --- extract A fragments (one slab: rows w*16..w*16+15) ---
    const int m0 = w * 16;
    uint32_t AH[4][4], AL[4][4];
    {
        const uint32_t r0 = (uint32_t)(m0 + g) * ESTRIDE;
        const uint32_t r8 = r0 + 8 * ESTRIDE;
#pragma unroll
        for (int ks = 0; ks < 4; ks++) {
            int c0 = 16 * ks + 2 * q;
            AH[ks][0] = *(const uint32_t*)&aHi[r0 + c0];
            AH[ks][1] = *(const uint32_t*)&aHi[r8 + c0];
            AH[ks][2] = *(const uint32_t*)&aHi[r0 + c0 + 8];
            AH[ks][3] = *(const uint32_t*)&aHi[r8 + c0 + 8];
            AL[ks][0] = *(const uint32_t*)&aLo[r0 + c0];
            AL[ks][1] = *(const uint32_t*)&aLo[r8 + c0];
            AL[ks][2] = *(const uint32_t*)&aLo[r0 + c0 + 8];
            AL[ks][3] = *(const uint32_t*)&aLo[r8 + c0 + 8];
        }
    }
    __syncthreads();   // frags extracted before BUF1 is overwritten (chunk 1)

    const uint32_t lmoff = (uint32_t)(((lane & 7) * ESTRIDE + (lane >> 3) * 8) * 2);
    const float* nebq = g_neb + 2 * q;

    float bv0 = -FLT_MAX, bv1 = -FLT_MAX;
    int   bk0 = 0, bk1 = 0;

    for (int c = 0; c < NCHUNKS; c++) {
        CP_WAIT0();            // chunk c landed
        __syncthreads();       // visible; all warps done with chunk c-1
        if (c + 1 < NCHUNKS) { copy_chunk(smb, c + 1, (c + 1) & 1, t); CP_COMMIT(); }

        const uint32_t boff = smb + ((c & 1) ? BUF1_OFF : BUF0_OFF);
        const uint32_t bhi = boff + lmoff;
        const uint32_t blo = boff + HALF_BUF + lmoff;
        const int kbase = c * CHUNK;

#pragma unroll 2
        for (int n8 = 0; n8 < CHUNK / 8; n8++) {
            const uint32_t adv = (uint32_t)n8 * 1152u;
            uint32_t h0, h1, h2, h3, h4, h5, h6, h7;
            uint32_t l0, l1, l2, l3, l4, l5, l6, l7;
            ldsm_x4(h0, h1, h2, h3, bhi + adv);
            ldsm_x4(h4, h5, h6, h7, bhi + adv + 64u);
            ldsm_x4(l0, l1, l2, l3, blo + adv);
            ldsm_x4(l4, l5, l6, l7, blo + adv + 64u);
            const float2 nb = __ldg((const float2*)(nebq + kbase + n8 * 8));

            // 3 independent 4-deep chains: xh*eh (bias), xh*el, xl*eh
            float d0, d1, d2, d3, u0, u1, u2, u3, v0, v1, v2, v3;
            mma_init(d0, d1, d2, d3, AH[0], h0, h1, nb.x, nb.y);
            mma_init(u0, u1, u2, u3, AH[0], l0, l1, 0.0f, 0.0f);
            mma_init(v0, v1, v2, v3, AL[0], h0, h1, 0.0f, 0.0f);
            mma_acc (d0, d1, d2, d3, AH[1], h2, h3);
            mma_acc (u0, u1, u2, u3, AH[1], l2, l3);
            mma_acc (v0, v1, v2, v3, AL[1], h2, h3);
            mma_acc (d0, d1, d2, d3, AH[2], h4, h5);
            mma_acc (u0, u1, u2, u3, AH[2], l4, l5);
            mma_acc (v0, v1, v2, v3, AL[2], h4, h5);
            mma_acc (d0, d1, d2, d3, AH[3], h6, h7);
            mma_acc (u0, u1, u2, u3, AH[3], l6, l7);
            mma_acc (v0, v1, v2, v3, AL[3], h6, h7);
            const float a0 = d0 + u0 + v0, a1 = d1 + u1 + v1;
            const float a2 = d2 + u2 + v2, a3 = d3 + u3 + v3;

            const int k0 = kbase + n8 * 8 + 2 * q;
            if (a0 > bv0) { bv0 = a0; bk0 = k0; }
            if (a1 > bv0) { bv0 = a1; bk0 = k0 + 1; }
            if (a2 > bv1) { bv1 = a2; bk1 = k0; }
            if (a3 > bv1) { bv1 = a3; bk1 = k0 + 1; }
        }
    }

    // --- quad reduce (tie-break to smaller k = first occurrence) ---
#pragma unroll
    for (int m = 1; m < 4; m <<= 1) {
        float v; int k;
        v = __shfl_xor_sync(0xffffffffu, bv0, m); k = __shfl_xor_sync(0xffffffffu, bk0, m);
        if (v > bv0 || (v == bv0 && k < bk0)) { bv0 = v; bk0 = k; }
        v = __shfl_xor_sync(0xffffffffu, bv1, m); k = __shfl_xor_sync(0xffffffffu, bk1, m);
        if (v > bv1 || (v == bv1 && k < bk1)) { bv1 = v; bk1 = k; }
    }
    {
        float vsum = (q == 0) ? (bv0 + bv1) : 0.0f;
#pragma unroll
        for (int off = 16; off > 0; off >>= 1)
            vsum += __shfl_down_sync(0xffffffffu, vsum, off);
        if (lane == 0) sred[8 + w] = vsum;
        if (q == 0) { sbk[m0 + g] = bk0; sbk[m0 + g + 8] = bk1; }
    }
    __syncthreads();

    // --- epilogue: indices, quantized gather (coalesced stores), loss ---
    {
        const int p = t & 127, ch = t >> 7;
        const int bk = sbk[p];
        if (ch == 0) out[OUT_IDX_OFF + (size_t)b_idx * SPATIAL + s0 + p] = (float)bk;
        const float4* er = (const float4*)(emb + (size_t)bk * DIM) + ch * 8;
        float* qo = out + OUT_Q_OFF + (size_t)b_idx * (DIM * SPATIAL) + s0 + p;
#pragma unroll
        for (int j = 0; j < 8; j++) {
            float4 e4 = er[j];
            int cc = ch * 32 + 4 * j;
            qo[(cc + 0) * SPATIAL] = e4.x;
            qo[(cc + 1) * SPATIAL] = e4.y;
            qo[(cc + 2) * SPATIAL] = e4.z;
            qo[(cc + 3) * SPATIAL] = e4.w;
        }
    }
    if (t == 0) {
        float sx = 0.0f, sv = 0.0f;
#pragma unroll
        for (int i = 0; i < 8; i++) { sx += sred[i]; sv += sred[8 + i]; }
        // sum ||q-x||^2 over tile = sum||x||^2 - 2 * sum v_best
        atomicAdd(out + OUT_LOSS_OFF, (sx - 2.0f * sv) * (0.25f / (float)Q_ELEMS));
    }
}

// ---------------------------------------------------------------------------
extern "C" void kernel_launch(void* const* d_in, const int* in_sizes, int n_in,
                              void* d_out, int out_size) {
    const float* x_in = (const float*)d_in[0];
    const float* emb  = (const float*)d_in[1];
    float* out = (float*)d_out;

    cudaFuncSetAttribute(vq_main_kernel,
                         cudaFuncAttributeMaxDynamicSharedMemorySize, SMEM_BYTES);

    vq_prep_kernel<<<32, 256>>>(emb, out);
    vq_main_kernel<<<(16 * SPATIAL) / TILE_M, 256, SMEM_BYTES>>>(x_in, emb, out);
}

// round 15
// speedup vs baseline: 1.2985x; 1.1349x over previous
#include <cuda_runtime.h>
#include <cuda_fp16.h>
#include <cstdint>
#include <cfloat>

// ---------------- problem constants ----------------
#define SPATIAL   4096
#define DIM       64
#define NCODES    1024
#define Q_ELEMS   4194304
#define OUT_LOSS_OFF 0
#define OUT_Q_OFF    1
#define OUT_IDX_OFF  (1 + Q_ELEMS)

#define TILE_M    256           // positions per CTA (2 m16 slabs per warp)
#define CHUNK     128           // codes per smem chunk
#define NCHUNKS   (NCODES / CHUNK)
#define ESTRIDE   72            // halves per row (144B): conflict-free LDS/LDSM

// smem layout (byte offsets). Buf1 (=offset 0) doubles as A staging (2 passes).
#define BUF1_OFF   0u           // hi 18432 + lo 18432 = 36864 B
#define BUF0_OFF   36864u
#define HALF_BUF   18432u
#define SM_NEB     73728        // 2 x 128 floats (1024 B)
#define SM_RED     74752        // 16 floats
#define SM_BK      74816        // 256 ints (1024 B)
#define SMEM_BYTES 75840

// ---------------- device scratch (pre-split, padded E) ----------------
__device__ __align__(16) __half g_ehi[NCODES * ESTRIDE];
__device__ __align__(16) __half g_elo[NCODES * ESTRIDE];
__device__ float g_neb[NCODES];     // -0.5 * ||e_k||^2

// ---------------- PTX helpers ----------------
__device__ __forceinline__ uint32_t smem_u32(const void* p) {
    uint32_t a;
    asm("{ .reg .u64 t; cvta.to.shared.u64 t, %1; cvt.u32.u64 %0, t; }" : "=r"(a) : "l"(p));
    return a;
}
#define CP16(dst, src)  asm volatile("cp.async.cg.shared.global [%0], [%1], 16;" :: "r"(dst), "l"(src))
#define CP_COMMIT()     asm volatile("cp.async.commit_group;" ::: "memory")
#define CP_WAIT0()      asm volatile("cp.async.wait_group 0;" ::: "memory")

__device__ __forceinline__ void ldsm_x4(uint32_t& r0, uint32_t& r1, uint32_t& r2,
                                        uint32_t& r3, uint32_t addr) {
    asm volatile("ldmatrix.sync.aligned.m8n8.x4.shared.b16 {%0,%1,%2,%3}, [%4];"
                 : "=r"(r0), "=r"(r1), "=r"(r2), "=r"(r3) : "r"(addr));
}
__device__ __forceinline__ void mma_init(float& d0, float& d1, float& d2, float& d3,
                                         const uint32_t* a, uint32_t b0, uint32_t b1,
                                         float cx, float cy) {
    asm volatile("mma.sync.aligned.m16n8k16.row.col.f32.f16.f16.f32 "
                 "{%0,%1,%2,%3}, {%4,%5,%6,%7}, {%8,%9}, {%10,%11,%10,%11};"
                 : "=f"(d0), "=f"(d1), "=f"(d2), "=f"(d3)
                 : "r"(a[0]), "r"(a[1]), "r"(a[2]), "r"(a[3]), "r"(b0), "r"(b1),
                   "f"(cx), "f"(cy));
}
__device__ __forceinline__ void mma_zero(float& d0, float& d1, float& d2, float& d3,
                                         const uint32_t* a, uint32_t b0, uint32_t b1) {
    asm volatile("{\n\t.reg .f32 z;\n\tmov.f32 z, 0f00000000;\n\t"
                 "mma.sync.aligned.m16n8k16.row.col.f32.f16.f16.f32 "
                 "{%0,%1,%2,%3}, {%4,%5,%6,%7}, {%8,%9}, {z, z, z, z};\n\t}"
                 : "=f"(d0), "=f"(d1), "=f"(d2), "=f"(d3)
                 : "r"(a[0]), "r"(a[1]), "r"(a[2]), "r"(a[3]), "r"(b0), "r"(b1));
}
__device__ __forceinline__ void mma_acc(float& d0, float& d1, float& d2, float& d3,
                                        const uint32_t* a, uint32_t b0, uint32_t b1) {
    asm volatile("mma.sync.aligned.m16n8k16.row.col.f32.f16.f16.f32 "
                 "{%0,%1,%2,%3}, {%4,%5,%6,%7}, {%8,%9}, {%0,%1,%2,%3};"
                 : "+f"(d0), "+f"(d1), "+f"(d2), "+f"(d3)
                 : "r"(a[0]), "r"(a[1]), "r"(a[2]), "r"(a[3]), "r"(b0), "r"(b1));
}

// ---------------------------------------------------------------------------
// Kernel 1: split E -> (hi, lo) f16, padded rows; neb; zero loss.
// 8192 threads: 8 threads per code row, 16B vector stores.
// ---------------------------------------------------------------------------
__global__ void vq_prep_kernel(const float* __restrict__ emb, float* __restrict__ out) {
    const int tid = blockIdx.x * blockDim.x + threadIdx.x;   // 0..8191
    if (tid == 0) out[OUT_LOSS_OFF] = 0.0f;
    const int r = tid >> 3, j = tid & 7;
    const float* e = emb + (size_t)r * DIM + j * 8;
    __half hi[8], lo[8];
    float s = 0.0f;
#pragma unroll
    for (int i = 0; i < 8; i++) {
        float v = e[i];
        s += v * v;
        hi[i] = __float2half_rn(v);
        lo[i] = __float2half_rn(v - __half2float(hi[i]));
    }
    *(uint4*)&g_ehi[r * ESTRIDE + j * 8] = *(const uint4*)hi;
    *(uint4*)&g_elo[r * ESTRIDE + j * 8] = *(const uint4*)lo;
#pragma unroll
    for (int off = 4; off > 0; off >>= 1)
        s += __shfl_down_sync(0xffffffffu, s, off, 8);
    if (j == 0) g_neb[r] = -0.5f * s;
}

// ---------------------------------------------------------------------------
// Chunk copy: E chunk c (hi+lo, 36864 B) + neb (512 B) via cp.async 16B.
// ---------------------------------------------------------------------------
__device__ __forceinline__ void copy_chunk(uint32_t smb, int c, int t) {
    const uint32_t off = (c & 1) ? BUF1_OFF : BUF0_OFF;
    const char* srcH = (const char*)(g_ehi + (size_t)c * CHUNK * ESTRIDE);
    const char* srcL = (const char*)(g_elo + (size_t)c * CHUNK * ESTRIDE);
    const uint32_t dH = smb + off;
    const uint32_t dL = smb + off + HALF_BUF;
#pragma unroll
    for (int i = t; i < 1152; i += 256) {
        CP16(dH + (uint32_t)i * 16u, srcH + (size_t)i * 16);
        CP16(dL + (uint32_t)i * 16u, srcL + (size_t)i * 16);
    }
    if (t < 32)
        CP16(smb + SM_NEB + (uint32_t)(c & 1) * 512u + (uint32_t)t * 16u,
             (const char*)(g_neb + c * CHUNK) + (size_t)t * 16);
}

// ---------------------------------------------------------------------------
// Kernel 2: fused HMMA GEMM + argmin + gather + loss.
// 256 positions/CTA, 8 warps, each warp = 2 m16 slabs sharing B frags.
// Per slab: 4-deep (xh*eh, bias-init) + 8-deep (xh*el, xl*eh) chains.
// ---------------------------------------------------------------------------
__global__ void __launch_bounds__(256, 2) vq_main_kernel(
    const float* __restrict__ x_in,   // [16,64,64,64] NCHW
    const float* __restrict__ emb,    // [1024,64] f32
    float* __restrict__ out)
{
    extern __shared__ char sm[];
    const uint32_t smb = smem_u32(sm);
    __half* aHi = (__half*)(sm + BUF1_OFF);             // A staging == buf1
    __half* aLo = (__half*)(sm + BUF1_OFF + HALF_BUF);
    float*  sred = (float*)(sm + SM_RED);
    int*    sbk  = (int*)(sm + SM_BK);

    const int t    = threadIdx.x;
    const int lane = t & 31;
    const int w    = t >> 5;
    const int g    = lane >> 2;
    const int q    = lane & 3;
    const int tile = blockIdx.x;
    const int b_idx = tile >> 4;               // 16 tiles per image
    const int s0    = (tile & 15) * TILE_M;
    const float* xbase = x_in + (size_t)b_idx * (DIM * SPATIAL) + s0;

    // kick off chunk 0 load into buf0 (overlaps X staging below)
    copy_chunk(smb, 0, t);
    CP_COMMIT();

    // --- stage X tile in 2 passes of 128 positions; extract A frags per slab ---
    const int m0 = w * 16;
    uint32_t AH[2][4][4], AL[2][4][4];
    float n2 = 0.0f;
#pragma unroll
    for (int pass = 0; pass < 2; pass++) {
        {
            int p = t & 127, ch = t >> 7;
            const float* xp = xbase + pass * 128 + p;
#pragma unroll
            for (int i = 0; i < 32; i++) {
                int c = ch * 32 + i;
                float v = xp[c * SPATIAL];
                n2 += v * v;
                __half h = __float2half_rn(v);
                aHi[p * ESTRIDE + c] = h;
                aLo[p * ESTRIDE + c] = __float2half_rn(v - __half2float(h));
            }
        }
        __syncthreads();
        {
            const uint32_t r0 = (uint32_t)(m0 + g) * ESTRIDE;
            const uint32_t r8 = r0 + 8 * ESTRIDE;
#pragma unroll
            for (int ks = 0; ks < 4; ks++) {
                int c0 = 16 * ks + 2 * q;
                AH[pass][ks][0] = *(const uint32_t*)&aHi[r0 + c0];
                AH[pass][ks][1] = *(const uint32_t*)&aHi[r8 + c0];
                AH[pass][ks][2] = *(const uint32_t*)&aHi[r0 + c0 + 8];
                AH[pass][ks][3] = *(const uint32_t*)&aHi[r8 + c0 + 8];
                AL[pass][ks][0] = *(const uint32_t*)&aLo[r0 + c0];
                AL[pass][ks][1] = *(const uint32_t*)&aLo[r8 + c0];
                AL[pass][ks][2] = *(const uint32_t*)&aLo[r0 + c0 + 8];
                AL[pass][ks][3] = *(const uint32_t*)&aLo[r8 + c0 + 8];
            }
        }
        __syncthreads();   // fragments extracted before buf1 is reused
    }
    // fold sum(x^2) now (A staging done)
#pragma unroll
    for (int off = 16; off > 0; off >>= 1)
        n2 += __shfl_down_sync(0xffffffffu, n2, off);
    if (lane == 0) sred[w] = n2;

    // per-lane ldmatrix base offset within a buffer (16B-aligned)
    const uint32_t lmoff = (uint32_t)(((lane & 7) * ESTRIDE + (lane >> 3) * 8) * 2);

    float bv0 = -FLT_MAX, bv1 = -FLT_MAX;
    float bv2 = -FLT_MAX, bv3 = -FLT_MAX;
    int   bk0 = 0, bk1 = 0, bk2 = 0, bk3 = 0;

    for (int c = 0; c < NCHUNKS; c++) {
        CP_WAIT0();            // chunk c landed
        __syncthreads();       // visible to all; all warps done with chunk c-1
        if (c + 1 < NCHUNKS) { copy_chunk(smb, c + 1, t); CP_COMMIT(); }

        const uint32_t boff = smb + ((c & 1) ? BUF1_OFF : BUF0_OFF);
        const uint32_t bhi = boff + lmoff;
        const uint32_t blo = boff + HALF_BUF + lmoff;
        const float* sneb = (const float*)(sm + SM_NEB + (c & 1) * 512);
        const int kbase = c * CHUNK;

#pragma unroll 2
        for (int n8 = 0; n8 < CHUNK / 8; n8++) {
            const uint32_t adv = (uint32_t)n8 * 1152u;
            uint32_t h0, h1, h2, h3, h4, h5, h6, h7;
            uint32_t l0, l1, l2, l3, l4, l5, l6, l7;
            ldsm_x4(h0, h1, h2, h3, bhi + adv);
            ldsm_x4(h4, h5, h6, h7, bhi + adv + 64u);
            ldsm_x4(l0, l1, l2, l3, blo + adv);
            ldsm_x4(l4, l5, l6, l7, blo + adv + 64u);
            float2 nb = *(const float2*)&sneb[n8 * 8 + 2 * q];

            // 4 independent chains: per slab, d (4-deep, bias) + u (8-deep)
            float d0, d1, d2, d3, e0, e1, e2, e3;
            float u0, u1, u2, u3, f0, f1, f2, f3;
            mma_init(d0, d1, d2, d3, AH[0][0], h0, h1, nb.x, nb.y);
            mma_init(e0, e1, e2, e3, AH[1][0], h0, h1, nb.x, nb.y);
            mma_zero(u0, u1, u2, u3, AH[0][0], l0, l1);
            mma_zero(f0, f1, f2, f3, AH[1][0], l0, l1);
            mma_acc (d0, d1, d2, d3, AH[0][1], h2, h3);
            mma_acc (e0, e1, e2, e3, AH[1][1], h2, h3);
            mma_acc (u0, u1, u2, u3, AH[0][1], l2, l3);
            mma_acc (f0, f1, f2, f3, AH[1][1], l2, l3);
            mma_acc (d0, d1, d2, d3, AH[0][2], h4, h5);
            mma_acc (e0, e1, e2, e3, AH[1][2], h4, h5);
            mma_acc (u0, u1, u2, u3, AH[0][2], l4, l5);
            mma_acc (f0, f1, f2, f3, AH[1][2], l4, l5);
            mma_acc (d0, d1, d2, d3, AH[0][3], h6, h7);
            mma_acc (e0, e1, e2, e3, AH[1][3], h6, h7);
            mma_acc (u0, u1, u2, u3, AH[0][3], l6, l7);
            mma_acc (f0, f1, f2, f3, AH[1][3], l6, l7);
            mma_acc (u0, u1, u2, u3, AL[0][0], h0, h1);
            mma_acc (f0, f1, f2, f3, AL[1][0], h0, h1);
            mma_acc (u0, u1, u2, u3, AL[0][1], h2, h3);
            mma_acc (f0, f1, f2, f3, AL[1][1], h2, h3);
            mma_acc (u0, u1, u2, u3, AL[0][2], h4, h5);
            mma_acc (f0, f1, f2, f3, AL[1][2], h4, h5);
            mma_acc (u0, u1, u2, u3, AL[0][3], h6, h7);
            mma_acc (f0, f1, f2, f3, AL[1][3], h6, h7);

            const float a0 = d0 + u0, a1 = d1 + u1, a2 = d2 + u2, a3 = d3 + u3;
            const float c0v = e0 + f0, c1v = e1 + f1, c2v = e2 + f2, c3v = e3 + f3;

            const int k0 = kbase + n8 * 8 + 2 * q;
            if (a0 > bv0)  { bv0 = a0;  bk0 = k0; }
            if (a1 > bv0)  { bv0 = a1;  bk0 = k0 + 1; }
            if (a2 > bv1)  { bv1 = a2;  bk1 = k0; }
            if (a3 > bv1)  { bv1 = a3;  bk1 = k0 + 1; }
            if (c0v > bv2) { bv2 = c0v; bk2 = k0; }
            if (c1v > bv2) { bv2 = c1v; bk2 = k0 + 1; }
            if (c2v > bv3) { bv3 = c2v; bk3 = k0; }
            if (c3v > bv3) { bv3 = c3v; bk3 = k0 + 1; }
        }
    }

    // --- quad reduce (tie-break to smaller k = first occurrence) ---
#pragma unroll
    for (int m = 1; m < 4; m <<= 1) {
        float v; int k;
        v = __shfl_xor_sync(0xffffffffu, bv0, m); k = __shfl_xor_sync(0xffffffffu, bk0, m);
        if (v > bv0 || (v == bv0 && k < bk0)) { bv0 = v; bk0 = k; }
        v = __shfl_xor_sync(0xffffffffu, bv1, m); k = __shfl_xor_sync(0xffffffffu, bk1, m);
        if (v > bv1 || (v == bv1 && k < bk1)) { bv1 = v; bk1 = k; }
        v = __shfl_xor_sync(0xffffffffu, bv2, m); k = __shfl_xor_sync(0xffffffffu, bk2, m);
        if (v > bv2 || (v == bv2 && k < bk2)) { bv2 = v; bk2 = k; }
        v = __shfl_xor_sync(0xffffffffu, bv3, m); k = __shfl_xor_sync(0xffffffffu, bk3, m);
        if (v > bv3 || (v == bv3 && k < bk3)) { bv3 = v; bk3 = k; }
    }
    {
        float vsum = (q == 0) ? (bv0 + bv1 + bv2 + bv3) : 0.0f;
#pragma unroll
        for (int off = 16; off > 0; off >>= 1)
            vsum += __shfl_down_sync(0xffffffffu, vsum, off);
        if (lane == 0) sred[8 + w] = vsum;
        if (q == 0) {
            sbk[m0 + g]             = bk0;
            sbk[m0 + g + 8]         = bk1;
            sbk[128 + m0 + g]       = bk2;
            sbk[128 + m0 + g + 8]   = bk3;
        }
    }
    __syncthreads();

    // --- epilogue: indices, quantized gather (coalesced stores), loss ---
    {
        int p = t;                       // one position per thread
        int bk = sbk[p];
        out[OUT_IDX_OFF + (size_t)b_idx * SPATIAL + s0 + p] = (float)bk;
        const float4* er = (const float4*)(emb + (size_t)bk * DIM);
        float* qo = out + OUT_Q_OFF + (size_t)b_idx * (DIM * SPATIAL) + s0 + p;
#pragma unroll
        for (int j = 0; j < 16; j++) {
            float4 e4 = er[j];
            int cc = 4 * j;
            qo[(cc + 0) * SPATIAL] = e4.x;
            qo[(cc + 1) * SPATIAL] = e4.y;
            qo[(cc + 2) * SPATIAL] = e4.z;
            qo[(cc + 3) * SPATIAL] = e4.w;
        }
    }
    if (t == 0) {
        float sx = 0.0f, sv = 0.0f;
#pragma unroll
        for (int i = 0; i < 8; i++) { sx += sred[i]; sv += sred[8 + i]; }
        // sum ||q-x||^2 over tile = sum||x||^2 - 2 * sum v_best
        atomicAdd(out + OUT_LOSS_OFF, (sx - 2.0f * sv) * (0.25f / (float)Q_ELEMS));
    }
}

// ---------------------------------------------------------------------------
extern "C" void kernel_launch(void* const* d_in, const int* in_sizes, int n_in,
                              void* d_out, int out_size) {
    const float* x_in = (const float*)d_in[0];
    const float* emb  = (const float*)d_in[1];
    float* out = (float*)d_out;

    cudaFuncSetAttribute(vq_main_kernel,
                         cudaFuncAttributeMaxDynamicSharedMemorySize, SMEM_BYTES);

    vq_prep_kernel<<<32, 256>>>(emb, out);
    vq_main_kernel<<<(16 * SPATIAL) / TILE_M, 256, SMEM_BYTES>>>(x_in, emb, out);
}